// round 4
// baseline (speedup 1.0000x reference)
#include <cuda_runtime.h>
#include <cuda_bf16.h>
#include <cstdint>
#include <math.h>

typedef unsigned long long ull;
typedef unsigned int u32;

// ======================= problem constants =======================
#define BATCH   2
#define SEQ     2048
#define EMB     2048
#define NHEAD   32
#define HDIM    64
#define BT      (BATCH*SEQ)      // 4096
#define N_QKV   (3*EMB)          // 6144
#define KP      6144             // split-K' = 3*2048

// ======================= scratch (device globals) ================
__device__ float g_qkv[(size_t)BT * N_QKV];
__device__ float g_q  [(size_t)BATCH*NHEAD*SEQ*HDIM];
__device__ float g_k  [(size_t)BATCH*NHEAD*SEQ*HDIM];
__device__ float g_v  [(size_t)BATCH*NHEAD*SEQ*HDIM];
__device__ float g_ao [(size_t)BT * EMB];
__device__ __nv_bfloat16 g_Ax  [(size_t)BT * KP];
__device__ __nv_bfloat16 g_Aao [(size_t)BT * KP];
__device__ __nv_bfloat16 g_Bqkv[(size_t)N_QKV * KP];
__device__ __nv_bfloat16 g_Bout[(size_t)EMB * KP];

// ======================= helpers =================================
__device__ __forceinline__ ull pack2(float lo, float hi){
    ull r; asm("mov.b64 %0, {%1,%2};" : "=l"(r) : "f"(lo), "f"(hi)); return r;
}
__device__ __forceinline__ float2 unpack2(ull v){
    float2 f; asm("mov.b64 {%0,%1}, %2;" : "=f"(f.x), "=f"(f.y) : "l"(v)); return f;
}
__device__ __forceinline__ void fma2(ull &c, ull a, ull b){
    asm("fma.rn.f32x2 %0, %1, %2, %0;" : "+l"(c) : "l"(a), "l"(b));
}
__device__ __forceinline__ void mul2(ull &c, ull b){
    asm("mul.rn.f32x2 %0, %0, %1;" : "+l"(c) : "l"(b));
}
__device__ __forceinline__ u32 smem_u32(const void* p){
    u32 a; asm("{ .reg .u64 t; cvta.to.shared.u64 t, %1; cvt.u32.u64 %0, t; }" : "=r"(a) : "l"(p));
    return a;
}
#define SWZ128(off) ((off) ^ (((off) >> 3) & 0x70))

__device__ __forceinline__ void cpasync16(u32 daddr, const void* gptr){
    asm volatile("cp.async.cg.shared.global [%0], [%1], 16;" :: "r"(daddr), "l"(gptr));
}
#define CP_COMMIT() asm volatile("cp.async.commit_group;")
#define CP_WAIT(n)  asm volatile("cp.async.wait_group %0;" :: "n"(n))

__device__ __forceinline__ void ldsm4(u32* r, u32 addr){
    asm volatile("ldmatrix.sync.aligned.m8n8.x4.shared.b16 {%0,%1,%2,%3}, [%4];"
        : "=r"(r[0]), "=r"(r[1]), "=r"(r[2]), "=r"(r[3]) : "r"(addr));
}
__device__ __forceinline__ void mma16816(float* c, const u32* a, u32 b0, u32 b1){
    asm volatile("mma.sync.aligned.m16n8k16.row.col.f32.bf16.bf16.f32 "
        "{%0,%1,%2,%3}, {%4,%5,%6,%7}, {%8,%9}, {%0,%1,%2,%3};"
        : "+f"(c[0]), "+f"(c[1]), "+f"(c[2]), "+f"(c[3])
        : "r"(a[0]), "r"(a[1]), "r"(a[2]), "r"(a[3]), "r"(b0), "r"(b1));
}

// =============================================================================
// Split conversions: fp32 -> bf16 (hi, hi, lo) rows [R, 2048] -> [R, 6144]
// =============================================================================
__global__ void split_rows(const float* __restrict__ X, __nv_bfloat16* __restrict__ Ap, int R)
{
    size_t idx = (size_t)blockIdx.x*blockDim.x + threadIdx.x;
    if (idx >= (size_t)R*512) return;
    int m  = (int)(idx >> 9);
    int c4 = (int)(idx & 511) * 4;
    float4 x = *(const float4*)(X + (size_t)m*2048 + c4);
    float xs[4] = {x.x, x.y, x.z, x.w};
    __nv_bfloat16 hi[4], lo[4];
    #pragma unroll
    for (int j=0;j<4;j++){
        hi[j] = __float2bfloat16(xs[j]);
        lo[j] = __float2bfloat16(xs[j] - __bfloat162float(hi[j]));
    }
    __nv_bfloat16* row = Ap + (size_t)m*KP;
    *(ull*)(row + c4)        = *(const ull*)hi;
    *(ull*)(row + 2048 + c4) = *(const ull*)hi;
    *(ull*)(row + 4096 + c4) = *(const ull*)lo;
}

// W [2048, N] fp32 -> Bp [N, 6144] bf16 (hi at k, lo at 2048+k, hi at 4096+k)
__global__ void split_BT(const float* __restrict__ W, __nv_bfloat16* __restrict__ Bp, int N)
{
    __shared__ float tile[32][33];
    const int n0 = blockIdx.x*32, k0 = blockIdx.y*32;
    const int tx = threadIdx.x, ty = threadIdx.y;
    #pragma unroll
    for (int j=0;j<4;j++)
        tile[ty*4+j][tx] = W[(size_t)(k0+ty*4+j)*N + n0 + tx];
    __syncthreads();
    #pragma unroll
    for (int j=0;j<4;j++){
        const float v = tile[tx][ty*4+j];
        const __nv_bfloat16 hi = __float2bfloat16(v);
        const __nv_bfloat16 lo = __float2bfloat16(v - __bfloat162float(hi));
        __nv_bfloat16* row = Bp + (size_t)(n0+ty*4+j)*KP + k0 + tx;
        row[0]    = hi;
        row[2048] = lo;
        row[4096] = hi;
    }
}

// =============================================================================
// HMMA GEMM v2: C[M,N] = A'[M,KP] * B'[N,KP]^T + bias
// 128x128 CTA, 4 warps (64x64 each), 3-stage cp.async ring, GK=64,
// SW128-swizzled smem, one __syncthreads per chunk.
// =============================================================================
#define GK 64
#define NC (KP/GK)              // 96
#define STAGE_A 16384           // 128 rows x 128B
#define STAGE_B 16384
#define STAGE   (STAGE_A + STAGE_B)    // 32 KB
#define NSTG 3
#define GEMM_SMEM (NSTG*STAGE)         // 96 KB

__global__ __launch_bounds__(128, 2)
void gemm_hmma(const __nv_bfloat16* __restrict__ A,
               const __nv_bfloat16* __restrict__ B,
               const float* __restrict__ bias,
               float* __restrict__ C, int N)
{
    extern __shared__ char smem[];
    const u32 sb = smem_u32(smem);
    const int tid  = threadIdx.x;
    const int wid  = tid >> 5;
    const int lane = tid & 31;
    const int wm = wid & 1;          // warp rows: wm*64..+63
    const int wn = wid >> 1;         // warp cols: wn*64..+63
    const int m0 = blockIdx.y * 128;
    const int n0 = blockIdx.x * 128;

    const __nv_bfloat16* Ab = A + (size_t)m0 * KP;
    const __nv_bfloat16* Bb = B + (size_t)n0 * KP;

    // per-thread load: row = tid (0..127), 8 granules of 16B for A and for B
    const int lr = tid;
    auto load_stage = [&](int kc, u32 off){
        const __nv_bfloat16* Ag = Ab + (size_t)lr*KP + kc*GK;
        const __nv_bfloat16* Bg = Bb + (size_t)lr*KP + kc*GK;
        #pragma unroll
        for (int j=0;j<8;j++)
            cpasync16(sb + off + SWZ128(lr*128 + j*16), Ag + j*8);
        #pragma unroll
        for (int j=0;j<8;j++)
            cpasync16(sb + off + STAGE_A + SWZ128(lr*128 + j*16), Bg + j*8);
    };

    float acc[4][8][4];
    #pragma unroll
    for (int a=0;a<4;a++)
        #pragma unroll
        for (int b=0;b<8;b++)
            #pragma unroll
            for (int c=0;c<4;c++) acc[a][b][c] = 0.f;

    load_stage(0, 0);         CP_COMMIT();
    load_stage(1, STAGE);     CP_COMMIT();

    // lane offsets for ldmatrix
    const int arow = wm*64 + (lane & 15);
    const int akof = (lane >> 4) * 8;
    const int brow = wn*64 + ((lane >> 4) & 1)*8 + (lane & 7);
    const int bkof = ((lane >> 3) & 1) * 8;

    int slot = 0;
    for (int i=0; i<NC; i++){
        CP_WAIT(1);
        __syncthreads();

        // prefetch stage i+2 into the slot freed by stage i-1
        if (i+2 < NC){
            int ns = slot + 2; if (ns >= NSTG) ns -= NSTG;
            load_stage(i+2, (u32)ns * STAGE);
        }
        CP_COMMIT();

        const u32 abase = sb + (u32)slot * STAGE;
        const u32 bbase = abase + STAGE_A;

        #pragma unroll
        for (int ks=0; ks<4; ks++){
            const int k0 = ks*16;
            u32 afr[4][4];
            #pragma unroll
            for (int mf=0; mf<4; mf++)
                ldsm4(afr[mf], abase + SWZ128((arow + mf*16)*128 + (k0 + akof)*2));
            u32 bfr[4][4];
            #pragma unroll
            for (int nq=0; nq<4; nq++)
                ldsm4(bfr[nq], bbase + SWZ128((brow + nq*16)*128 + (k0 + bkof)*2));
            #pragma unroll
            for (int mf=0; mf<4; mf++)
                #pragma unroll
                for (int nq=0; nq<4; nq++){
                    mma16816(acc[mf][nq*2+0], afr[mf], bfr[nq][0], bfr[nq][1]);
                    mma16816(acc[mf][nq*2+1], afr[mf], bfr[nq][2], bfr[nq][3]);
                }
        }
        slot++; if (slot >= NSTG) slot = 0;
    }

    // epilogue
    #pragma unroll
    for (int mf=0; mf<4; mf++){
        const int r = m0 + wm*64 + mf*16 + (lane >> 2);
        #pragma unroll
        for (int nf=0; nf<8; nf++){
            const int c = n0 + wn*64 + nf*8 + (lane & 3)*2;
            const float b0 = bias[c], b1 = bias[c+1];
            float* cp = C + (size_t)r*N + c;
            *(float2*)cp = make_float2(acc[mf][nf][0] + b0, acc[mf][nf][1] + b1);
            *(float2*)(cp + 8*(size_t)N) = make_float2(acc[mf][nf][2] + b0, acc[mf][nf][3] + b1);
        }
    }
}

// =============================================================================
// RoPE + scatter
// =============================================================================
__global__ void rope_scatter(const float* __restrict__ qkv,
                             float* __restrict__ q, float* __restrict__ k,
                             float* __restrict__ v)
{
    const int bt = blockIdx.x;
    const int b = bt >> 11, t = bt & 2047;
    const float* row = qkv + (size_t)bt * N_QKV;

    for (int e = threadIdx.x; e < EMB; e += blockDim.x){
        const int h = e >> 6, d = e & 63;
        const size_t dst = ((size_t)(b*NHEAD + h) * SEQ + t) * HDIM + d;
        float qv = row[e];
        float kv = row[EMB + e];
        const float vv = row[2*EMB + e];
        if (d < 32){
            const int i = d & 15;
            const float invf = expf(-(float)i * (9.210340371976184f / 16.0f));
            const float ang = (float)t * invf;
            float sn, cs; sincosf(ang, &sn, &cs);
            if (d < 16){
                const float qx2 = row[e + 16];
                const float kx2 = row[EMB + e + 16];
                qv = qv*cs - qx2*sn;
                kv = kv*cs - kx2*sn;
            } else {
                const float qx1 = row[e - 16];
                const float kx1 = row[EMB + e - 16];
                qv = qx1*sn + qv*cs;
                kv = kx1*sn + kv*cs;
            }
        }
        q[dst] = qv * 0.125f;
        k[dst] = kv;
        v[dst] = vv;
    }
}

// =============================================================================
// Flash attention fp32, causal (f32x2 FMA path)
// =============================================================================
#define PAD 68
__global__ __launch_bounds__(256)
void flash_attn(const float* __restrict__ Q, const float* __restrict__ K,
                const float* __restrict__ V, float* __restrict__ Oo)
{
    extern __shared__ float sm[];
    float* Qs = sm;
    float* Ks = sm + 64*PAD;
    float* Vs = sm + 2*64*PAD;
    float* Ps = sm + 3*64*PAD;

    const int tid = threadIdx.x;
    const int tr = tid >> 4, tc = tid & 15;
    const int qt = blockIdx.x;
    const int bh = blockIdx.y;
    const size_t base = (size_t)bh * SEQ * HDIM;

    #pragma unroll
    for (int l=0;l<16;l++){
        int idx = tid + l*256;
        int r = idx >> 6, d = idx & 63;
        Qs[d*PAD + r] = Q[base + (size_t)(qt*64 + r)*HDIM + d];
    }

    float m[4], lsum[4];
    #pragma unroll
    for (int i=0;i<4;i++){ m[i] = -1e30f; lsum[i] = 0.f; }
    ull o2[4][2];
    #pragma unroll
    for (int i=0;i<4;i++){ o2[i][0]=0ULL; o2[i][1]=0ULL; }

    for (int kt = 0; kt <= qt; kt++){
        __syncthreads();
        #pragma unroll
        for (int l=0;l<16;l++){
            int idx = tid + l*256;
            int c = idx >> 6, d = idx & 63;
            Ks[d*PAD + c] = K[base + (size_t)(kt*64 + c)*HDIM + d];
            Vs[c*PAD + d] = V[base + (size_t)(kt*64 + c)*HDIM + d];
        }
        __syncthreads();

        ull s2[4][2];
        #pragma unroll
        for (int i=0;i<4;i++){ s2[i][0]=0ULL; s2[i][1]=0ULL; }
        #pragma unroll 8
        for (int d=0; d<64; d++){
            const float4 qv = *(const float4*)&Qs[d*PAD + tr*4];
            const ull* kp = (const ull*)&Ks[d*PAD + tc*4];
            const ull kb0 = kp[0], kb1 = kp[1];
            const float qa[4] = {qv.x, qv.y, qv.z, qv.w};
            #pragma unroll
            for (int i=0;i<4;i++){
                ull pa = pack2(qa[i], qa[i]);
                fma2(s2[i][0], pa, kb0);
                fma2(s2[i][1], pa, kb1);
            }
        }

        #pragma unroll
        for (int i=0;i<4;i++){
            float2 x0 = unpack2(s2[i][0]);
            float2 x1 = unpack2(s2[i][1]);
            float s0=x0.x, s1=x0.y, s2f=x1.x, s3=x1.y;
            if (kt == qt){
                const int rg = tr*4 + i;
                if (tc*4+0 > rg) s0  = -1e30f;
                if (tc*4+1 > rg) s1  = -1e30f;
                if (tc*4+2 > rg) s2f = -1e30f;
                if (tc*4+3 > rg) s3  = -1e30f;
            }
            float rm = fmaxf(fmaxf(s0,s1), fmaxf(s2f,s3));
            #pragma unroll
            for (int off=8; off; off>>=1)
                rm = fmaxf(rm, __shfl_xor_sync(0xffffffffu, rm, off));
            const float mn = fmaxf(m[i], rm);
            const float p0 = __expf(s0 - mn);
            const float p1 = __expf(s1 - mn);
            const float p2 = __expf(s2f - mn);
            const float p3 = __expf(s3 - mn);
            float rs = p0+p1+p2+p3;
            #pragma unroll
            for (int off=8; off; off>>=1)
                rs += __shfl_xor_sync(0xffffffffu, rs, off);
            const float corr = __expf(m[i] - mn);
            lsum[i] = lsum[i]*corr + rs;
            m[i] = mn;
            const ull pc = pack2(corr, corr);
            mul2(o2[i][0], pc);
            mul2(o2[i][1], pc);
            const int rr = tr*4 + i;
            Ps[(tc*4+0)*PAD + rr] = p0;
            Ps[(tc*4+1)*PAD + rr] = p1;
            Ps[(tc*4+2)*PAD + rr] = p2;
            Ps[(tc*4+3)*PAD + rr] = p3;
        }
        __syncthreads();

        #pragma unroll 8
        for (int c=0; c<64; c++){
            const float4 pv = *(const float4*)&Ps[c*PAD + tr*4];
            const ull* vp = (const ull*)&Vs[c*PAD + tc*4];
            const ull vb0 = vp[0], vb1 = vp[1];
            const float pa4[4] = {pv.x, pv.y, pv.z, pv.w};
            #pragma unroll
            for (int i=0;i<4;i++){
                ull pa = pack2(pa4[i], pa4[i]);
                fma2(o2[i][0], pa, vb0);
                fma2(o2[i][1], pa, vb1);
            }
        }
    }

    const int b = bh >> 5, h = bh & 31;
    #pragma unroll
    for (int i=0;i<4;i++){
        const float inv = 1.0f / lsum[i];
        float2 x0 = unpack2(o2[i][0]);
        float2 x1 = unpack2(o2[i][1]);
        const int t = qt*64 + tr*4 + i;
        float* op = Oo + ((size_t)(b*SEQ + t))*EMB + h*HDIM + tc*4;
        *(float4*)op = make_float4(x0.x*inv, x0.y*inv, x1.x*inv, x1.y*inv);
    }
}

// =============================================================================
extern "C" void kernel_launch(void* const* d_in, const int* in_sizes, int n_in,
                              void* d_out, int out_size)
{
    (void)in_sizes; (void)n_in; (void)out_size;
    const float* x    = (const float*)d_in[0];
    const float* Wqkv = (const float*)d_in[1];
    const float* bqkv = (const float*)d_in[2];
    const float* Wout = (const float*)d_in[3];
    const float* bout = (const float*)d_in[4];
    float* out = (float*)d_out;

    float *qkv, *q, *k, *v, *ao;
    __nv_bfloat16 *Ax, *Aao, *Bqkv, *Bout;
    cudaGetSymbolAddress((void**)&qkv, g_qkv);
    cudaGetSymbolAddress((void**)&q,   g_q);
    cudaGetSymbolAddress((void**)&k,   g_k);
    cudaGetSymbolAddress((void**)&v,   g_v);
    cudaGetSymbolAddress((void**)&ao,  g_ao);
    cudaGetSymbolAddress((void**)&Ax,   g_Ax);
    cudaGetSymbolAddress((void**)&Aao,  g_Aao);
    cudaGetSymbolAddress((void**)&Bqkv, g_Bqkv);
    cudaGetSymbolAddress((void**)&Bout, g_Bout);

    cudaFuncSetAttribute(gemm_hmma, cudaFuncAttributeMaxDynamicSharedMemorySize, GEMM_SMEM);

    // 0) split conversions
    split_rows<<<(BT*512 + 255)/256, 256>>>(x, Ax, BT);
    split_BT<<<dim3(N_QKV/32, EMB/32), dim3(32,8)>>>(Wqkv, Bqkv, N_QKV);
    split_BT<<<dim3(EMB/32,  EMB/32), dim3(32,8)>>>(Wout, Bout, EMB);

    // 1) QKV projection (tensor cores, mma.sync)
    gemm_hmma<<<dim3(N_QKV/128, BT/128), 128, GEMM_SMEM>>>(Ax, Bqkv, bqkv, qkv, N_QKV);

    // 2) RoPE + scatter
    rope_scatter<<<BT, 256>>>(qkv, q, k, v);

    // 3) causal flash attention (fp32)
    const int smem = 4 * 64 * PAD * (int)sizeof(float);
    cudaFuncSetAttribute(flash_attn, cudaFuncAttributeMaxDynamicSharedMemorySize, smem);
    flash_attn<<<dim3(SEQ/64, BATCH*NHEAD), 256, smem>>>(q, k, v, ao);

    // 4) output projection (tensor cores, mma.sync)
    split_rows<<<(BT*512 + 255)/256, 256>>>(ao, Aao, BT);
    gemm_hmma<<<dim3(EMB/128, BT/128), 128, GEMM_SMEM>>>(Aao, Bout, bout, out, EMB);
}

// round 5
// speedup vs baseline: 1.2909x; 1.2909x over previous
#include <cuda_runtime.h>
#include <cuda_bf16.h>
#include <cstdint>
#include <math.h>

typedef unsigned long long ull;
typedef unsigned int u32;

// ======================= problem constants =======================
#define BATCH   2
#define SEQ     2048
#define EMB     2048
#define NHEAD   32
#define HDIM    64
#define BT      (BATCH*SEQ)      // 4096
#define N_QKV   (3*EMB)          // 6144
#define KP      6144             // split-K' = 3*2048

// ======================= scratch (device globals) ================
__device__ float g_qkv[(size_t)BT * N_QKV];
__device__ float g_q  [(size_t)BATCH*NHEAD*SEQ*HDIM];
__device__ float g_k  [(size_t)BATCH*NHEAD*SEQ*HDIM];
__device__ float g_v  [(size_t)BATCH*NHEAD*SEQ*HDIM];
__device__ float g_ao [(size_t)BT * EMB];
__device__ __nv_bfloat16 g_Ax  [(size_t)BT * KP];
__device__ __nv_bfloat16 g_Aao [(size_t)BT * KP];
__device__ __nv_bfloat16 g_Bqkv[(size_t)N_QKV * KP];
__device__ __nv_bfloat16 g_Bout[(size_t)EMB * KP];

// ======================= helpers =================================
__device__ __forceinline__ ull pack2(float lo, float hi){
    ull r; asm("mov.b64 %0, {%1,%2};" : "=l"(r) : "f"(lo), "f"(hi)); return r;
}
__device__ __forceinline__ float2 unpack2(ull v){
    float2 f; asm("mov.b64 {%0,%1}, %2;" : "=f"(f.x), "=f"(f.y) : "l"(v)); return f;
}
__device__ __forceinline__ void fma2(ull &c, ull a, ull b){
    asm("fma.rn.f32x2 %0, %1, %2, %0;" : "+l"(c) : "l"(a), "l"(b));
}
__device__ __forceinline__ void mul2(ull &c, ull b){
    asm("mul.rn.f32x2 %0, %0, %1;" : "+l"(c) : "l"(b));
}
__device__ __forceinline__ u32 smem_u32(const void* p){
    u32 a; asm("{ .reg .u64 t; cvta.to.shared.u64 t, %1; cvt.u32.u64 %0, t; }" : "=r"(a) : "l"(p));
    return a;
}
#define SWZ128(off) ((off) ^ (((off) >> 3) & 0x70))

__device__ __forceinline__ void cpasync16(u32 daddr, const void* gptr){
    asm volatile("cp.async.cg.shared.global [%0], [%1], 16;" :: "r"(daddr), "l"(gptr));
}
#define CP_COMMIT() asm volatile("cp.async.commit_group;")
#define CP_WAIT(n)  asm volatile("cp.async.wait_group %0;" :: "n"(n))

__device__ __forceinline__ void ldsm4(u32* r, u32 addr){
    asm volatile("ldmatrix.sync.aligned.m8n8.x4.shared.b16 {%0,%1,%2,%3}, [%4];"
        : "=r"(r[0]), "=r"(r[1]), "=r"(r[2]), "=r"(r[3]) : "r"(addr));
}
__device__ __forceinline__ void mma16816(float* c, const u32* a, u32 b0, u32 b1){
    asm volatile("mma.sync.aligned.m16n8k16.row.col.f32.bf16.bf16.f32 "
        "{%0,%1,%2,%3}, {%4,%5,%6,%7}, {%8,%9}, {%0,%1,%2,%3};"
        : "+f"(c[0]), "+f"(c[1]), "+f"(c[2]), "+f"(c[3])
        : "r"(a[0]), "r"(a[1]), "r"(a[2]), "r"(a[3]), "r"(b0), "r"(b1));
}

// =============================================================================
// Split conversions: fp32 -> bf16 (hi, hi, lo) rows [R, 2048] -> [R, 6144]
// =============================================================================
__global__ void split_rows(const float* __restrict__ X, __nv_bfloat16* __restrict__ Ap, int R)
{
    size_t idx = (size_t)blockIdx.x*blockDim.x + threadIdx.x;
    if (idx >= (size_t)R*512) return;
    int m  = (int)(idx >> 9);
    int c4 = (int)(idx & 511) * 4;
    float4 x = *(const float4*)(X + (size_t)m*2048 + c4);
    float xs[4] = {x.x, x.y, x.z, x.w};
    __nv_bfloat16 hi[4], lo[4];
    #pragma unroll
    for (int j=0;j<4;j++){
        hi[j] = __float2bfloat16(xs[j]);
        lo[j] = __float2bfloat16(xs[j] - __bfloat162float(hi[j]));
    }
    __nv_bfloat16* row = Ap + (size_t)m*KP;
    *(ull*)(row + c4)        = *(const ull*)hi;
    *(ull*)(row + 2048 + c4) = *(const ull*)hi;
    *(ull*)(row + 4096 + c4) = *(const ull*)lo;
}

// W [2048, N] fp32 -> Bp [N, 6144] bf16 (hi at k, lo at 2048+k, hi at 4096+k)
__global__ void split_BT(const float* __restrict__ W, __nv_bfloat16* __restrict__ Bp, int N)
{
    __shared__ float tile[32][33];
    const int n0 = blockIdx.x*32, k0 = blockIdx.y*32;
    const int tx = threadIdx.x, ty = threadIdx.y;
    #pragma unroll
    for (int j=0;j<4;j++)
        tile[ty*4+j][tx] = W[(size_t)(k0+ty*4+j)*N + n0 + tx];
    __syncthreads();
    #pragma unroll
    for (int j=0;j<4;j++){
        const float v = tile[tx][ty*4+j];
        const __nv_bfloat16 hi = __float2bfloat16(v);
        const __nv_bfloat16 lo = __float2bfloat16(v - __bfloat162float(hi));
        __nv_bfloat16* row = Bp + (size_t)(n0+ty*4+j)*KP + k0 + tx;
        row[0]    = hi;
        row[2048] = lo;
        row[4096] = hi;
    }
}

// =============================================================================
// HMMA GEMM v3: C[M,N] = A'[M,KP] * B'[N,KP]^T + bias
// 128x128 CTA, 8 warps (32x64 each), 3-stage cp.async ring, GK=64,
// SW128-swizzled smem, ONE __syncthreads per chunk.
// =============================================================================
#define GK 64
#define NC (KP/GK)              // 96
#define STAGE_A 16384           // 128 rows x 128B
#define STAGE_B 16384
#define STAGE   (STAGE_A + STAGE_B)    // 32 KB
#define NSTG 3
#define GEMM_SMEM (NSTG*STAGE)         // 96 KB

__global__ __launch_bounds__(256, 2)
void gemm_hmma(const __nv_bfloat16* __restrict__ A,
               const __nv_bfloat16* __restrict__ B,
               const float* __restrict__ bias,
               float* __restrict__ C, int N)
{
    extern __shared__ char smem[];
    const u32 sb = smem_u32(smem);
    const int tid  = threadIdx.x;
    const int wid  = tid >> 5;
    const int lane = tid & 31;
    const int wm = wid & 3;          // warp rows: wm*32..+31
    const int wn = wid >> 2;         // warp cols: wn*64..+63
    const int m0 = blockIdx.y * 128;
    const int n0 = blockIdx.x * 128;

    const __nv_bfloat16* Ab = A + (size_t)m0 * KP;
    const __nv_bfloat16* Bb = B + (size_t)n0 * KP;

    // per-stage load: 128 rows x 8 granules (16B) for A and B; 256 threads
    const int lr  = tid >> 1;              // 0..127 row
    const int lk  = (tid & 1) * 4;         // granule 0 or 4
    auto load_stage = [&](int kc, u32 off){
        const __nv_bfloat16* Ag = Ab + (size_t)lr*KP + kc*GK + lk*8;
        const __nv_bfloat16* Bg = Bb + (size_t)lr*KP + kc*GK + lk*8;
        #pragma unroll
        for (int j=0;j<4;j++){
            cpasync16(sb + off           + SWZ128(lr*128 + (lk+j)*16), Ag + j*8);
            cpasync16(sb + off + STAGE_A + SWZ128(lr*128 + (lk+j)*16), Bg + j*8);
        }
    };

    float acc[2][8][4];
    #pragma unroll
    for (int a=0;a<2;a++)
        #pragma unroll
        for (int b=0;b<8;b++)
            #pragma unroll
            for (int c=0;c<4;c++) acc[a][b][c] = 0.f;

    load_stage(0, 0);       CP_COMMIT();
    load_stage(1, STAGE);   CP_COMMIT();

    // ldmatrix lane offsets
    const int arow = wm*32 + (lane & 15);
    const int akof = (lane >> 4) * 8;
    const int brow = wn*64 + ((lane >> 4) & 1)*8 + (lane & 7);
    const int bkof = ((lane >> 3) & 1) * 8;

    int slot = 0;
    for (int i=0; i<NC; i++){
        CP_WAIT(1);
        __syncthreads();

        // prefetch stage i+2 into slot freed by stage i-1 (safe past the barrier)
        if (i+2 < NC){
            int ns = slot + 2; if (ns >= NSTG) ns -= NSTG;
            load_stage(i+2, (u32)ns * STAGE);
        }
        CP_COMMIT();

        const u32 abase = sb + (u32)slot * STAGE;
        const u32 bbase = abase + STAGE_A;

        #pragma unroll
        for (int ks=0; ks<4; ks++){
            const int k0 = ks*16;
            u32 afr[2][4];
            #pragma unroll
            for (int mf=0; mf<2; mf++)
                ldsm4(afr[mf], abase + SWZ128((arow + mf*16)*128 + (k0 + akof)*2));
            u32 bfr[4][4];
            #pragma unroll
            for (int nq=0; nq<4; nq++)
                ldsm4(bfr[nq], bbase + SWZ128((brow + nq*16)*128 + (k0 + bkof)*2));
            #pragma unroll
            for (int mf=0; mf<2; mf++)
                #pragma unroll
                for (int nq=0; nq<4; nq++){
                    mma16816(acc[mf][nq*2+0], afr[mf], bfr[nq][0], bfr[nq][1]);
                    mma16816(acc[mf][nq*2+1], afr[mf], bfr[nq][2], bfr[nq][3]);
                }
        }
        slot++; if (slot >= NSTG) slot = 0;
    }

    // epilogue
    #pragma unroll
    for (int mf=0; mf<2; mf++){
        const int r = m0 + wm*32 + mf*16 + (lane >> 2);
        #pragma unroll
        for (int nf=0; nf<8; nf++){
            const int c = n0 + wn*64 + nf*8 + (lane & 3)*2;
            const float b0 = bias[c], b1 = bias[c+1];
            float* cp = C + (size_t)r*N + c;
            *(float2*)cp = make_float2(acc[mf][nf][0] + b0, acc[mf][nf][1] + b1);
            *(float2*)(cp + 8*(size_t)N) = make_float2(acc[mf][nf][2] + b0, acc[mf][nf][3] + b1);
        }
    }
}

// =============================================================================
// RoPE + scatter
// =============================================================================
__global__ void rope_scatter(const float* __restrict__ qkv,
                             float* __restrict__ q, float* __restrict__ k,
                             float* __restrict__ v)
{
    const int bt = blockIdx.x;
    const int b = bt >> 11, t = bt & 2047;
    const float* row = qkv + (size_t)bt * N_QKV;

    for (int e = threadIdx.x; e < EMB; e += blockDim.x){
        const int h = e >> 6, d = e & 63;
        const size_t dst = ((size_t)(b*NHEAD + h) * SEQ + t) * HDIM + d;
        float qv = row[e];
        float kv = row[EMB + e];
        const float vv = row[2*EMB + e];
        if (d < 32){
            const int i = d & 15;
            const float invf = expf(-(float)i * (9.210340371976184f / 16.0f));
            const float ang = (float)t * invf;
            float sn, cs; sincosf(ang, &sn, &cs);
            if (d < 16){
                const float qx2 = row[e + 16];
                const float kx2 = row[EMB + e + 16];
                qv = qv*cs - qx2*sn;
                kv = kv*cs - kx2*sn;
            } else {
                const float qx1 = row[e - 16];
                const float kx1 = row[EMB + e - 16];
                qv = qx1*sn + qv*cs;
                kv = kx1*sn + kv*cs;
            }
        }
        q[dst] = qv * 0.125f;
        k[dst] = kv;
        v[dst] = vv;
    }
}

// =============================================================================
// Flash attention fp32, causal (f32x2 FMA path)
// =============================================================================
#define PAD 68
__global__ __launch_bounds__(256)
void flash_attn(const float* __restrict__ Q, const float* __restrict__ K,
                const float* __restrict__ V, float* __restrict__ Oo)
{
    extern __shared__ float sm[];
    float* Qs = sm;
    float* Ks = sm + 64*PAD;
    float* Vs = sm + 2*64*PAD;
    float* Ps = sm + 3*64*PAD;

    const int tid = threadIdx.x;
    const int tr = tid >> 4, tc = tid & 15;
    const int qt = blockIdx.x;
    const int bh = blockIdx.y;
    const size_t base = (size_t)bh * SEQ * HDIM;

    #pragma unroll
    for (int l=0;l<16;l++){
        int idx = tid + l*256;
        int r = idx >> 6, d = idx & 63;
        Qs[d*PAD + r] = Q[base + (size_t)(qt*64 + r)*HDIM + d];
    }

    float m[4], lsum[4];
    #pragma unroll
    for (int i=0;i<4;i++){ m[i] = -1e30f; lsum[i] = 0.f; }
    ull o2[4][2];
    #pragma unroll
    for (int i=0;i<4;i++){ o2[i][0]=0ULL; o2[i][1]=0ULL; }

    for (int kt = 0; kt <= qt; kt++){
        __syncthreads();
        #pragma unroll
        for (int l=0;l<16;l++){
            int idx = tid + l*256;
            int c = idx >> 6, d = idx & 63;
            Ks[d*PAD + c] = K[base + (size_t)(kt*64 + c)*HDIM + d];
            Vs[c*PAD + d] = V[base + (size_t)(kt*64 + c)*HDIM + d];
        }
        __syncthreads();

        ull s2[4][2];
        #pragma unroll
        for (int i=0;i<4;i++){ s2[i][0]=0ULL; s2[i][1]=0ULL; }
        #pragma unroll 8
        for (int d=0; d<64; d++){
            const float4 qv = *(const float4*)&Qs[d*PAD + tr*4];
            const ull* kp = (const ull*)&Ks[d*PAD + tc*4];
            const ull kb0 = kp[0], kb1 = kp[1];
            const float qa[4] = {qv.x, qv.y, qv.z, qv.w};
            #pragma unroll
            for (int i=0;i<4;i++){
                ull pa = pack2(qa[i], qa[i]);
                fma2(s2[i][0], pa, kb0);
                fma2(s2[i][1], pa, kb1);
            }
        }

        #pragma unroll
        for (int i=0;i<4;i++){
            float2 x0 = unpack2(s2[i][0]);
            float2 x1 = unpack2(s2[i][1]);
            float s0=x0.x, s1=x0.y, s2f=x1.x, s3=x1.y;
            if (kt == qt){
                const int rg = tr*4 + i;
                if (tc*4+0 > rg) s0  = -1e30f;
                if (tc*4+1 > rg) s1  = -1e30f;
                if (tc*4+2 > rg) s2f = -1e30f;
                if (tc*4+3 > rg) s3  = -1e30f;
            }
            float rm = fmaxf(fmaxf(s0,s1), fmaxf(s2f,s3));
            #pragma unroll
            for (int off=8; off; off>>=1)
                rm = fmaxf(rm, __shfl_xor_sync(0xffffffffu, rm, off));
            const float mn = fmaxf(m[i], rm);
            const float p0 = __expf(s0 - mn);
            const float p1 = __expf(s1 - mn);
            const float p2 = __expf(s2f - mn);
            const float p3 = __expf(s3 - mn);
            float rs = p0+p1+p2+p3;
            #pragma unroll
            for (int off=8; off; off>>=1)
                rs += __shfl_xor_sync(0xffffffffu, rs, off);
            const float corr = __expf(m[i] - mn);
            lsum[i] = lsum[i]*corr + rs;
            m[i] = mn;
            const ull pc = pack2(corr, corr);
            mul2(o2[i][0], pc);
            mul2(o2[i][1], pc);
            const int rr = tr*4 + i;
            Ps[(tc*4+0)*PAD + rr] = p0;
            Ps[(tc*4+1)*PAD + rr] = p1;
            Ps[(tc*4+2)*PAD + rr] = p2;
            Ps[(tc*4+3)*PAD + rr] = p3;
        }
        __syncthreads();

        #pragma unroll 8
        for (int c=0; c<64; c++){
            const float4 pv = *(const float4*)&Ps[c*PAD + tr*4];
            const ull* vp = (const ull*)&Vs[c*PAD + tc*4];
            const ull vb0 = vp[0], vb1 = vp[1];
            const float pa4[4] = {pv.x, pv.y, pv.z, pv.w};
            #pragma unroll
            for (int i=0;i<4;i++){
                ull pa = pack2(pa4[i], pa4[i]);
                fma2(o2[i][0], pa, vb0);
                fma2(o2[i][1], pa, vb1);
            }
        }
    }

    const int b = bh >> 5, h = bh & 31;
    #pragma unroll
    for (int i=0;i<4;i++){
        const float inv = 1.0f / lsum[i];
        float2 x0 = unpack2(o2[i][0]);
        float2 x1 = unpack2(o2[i][1]);
        const int t = qt*64 + tr*4 + i;
        float* op = Oo + ((size_t)(b*SEQ + t))*EMB + h*HDIM + tc*4;
        *(float4*)op = make_float4(x0.x*inv, x0.y*inv, x1.x*inv, x1.y*inv);
    }
}

// =============================================================================
extern "C" void kernel_launch(void* const* d_in, const int* in_sizes, int n_in,
                              void* d_out, int out_size)
{
    (void)in_sizes; (void)n_in; (void)out_size;
    const float* x    = (const float*)d_in[0];
    const float* Wqkv = (const float*)d_in[1];
    const float* bqkv = (const float*)d_in[2];
    const float* Wout = (const float*)d_in[3];
    const float* bout = (const float*)d_in[4];
    float* out = (float*)d_out;

    float *qkv, *q, *k, *v, *ao;
    __nv_bfloat16 *Ax, *Aao, *Bqkv, *Bout;
    cudaGetSymbolAddress((void**)&qkv, g_qkv);
    cudaGetSymbolAddress((void**)&q,   g_q);
    cudaGetSymbolAddress((void**)&k,   g_k);
    cudaGetSymbolAddress((void**)&v,   g_v);
    cudaGetSymbolAddress((void**)&ao,  g_ao);
    cudaGetSymbolAddress((void**)&Ax,   g_Ax);
    cudaGetSymbolAddress((void**)&Aao,  g_Aao);
    cudaGetSymbolAddress((void**)&Bqkv, g_Bqkv);
    cudaGetSymbolAddress((void**)&Bout, g_Bout);

    cudaFuncSetAttribute(gemm_hmma, cudaFuncAttributeMaxDynamicSharedMemorySize, GEMM_SMEM);

    // 0) split conversions
    split_rows<<<(BT*512 + 255)/256, 256>>>(x, Ax, BT);
    split_BT<<<dim3(N_QKV/32, EMB/32), dim3(32,8)>>>(Wqkv, Bqkv, N_QKV);
    split_BT<<<dim3(EMB/32,  EMB/32), dim3(32,8)>>>(Wout, Bout, EMB);

    // 1) QKV projection (tensor cores, mma.sync)
    gemm_hmma<<<dim3(N_QKV/128, BT/128), 256, GEMM_SMEM>>>(Ax, Bqkv, bqkv, qkv, N_QKV);

    // 2) RoPE + scatter
    rope_scatter<<<BT, 256>>>(qkv, q, k, v);

    // 3) causal flash attention (fp32)
    const int smem = 4 * 64 * PAD * (int)sizeof(float);
    cudaFuncSetAttribute(flash_attn, cudaFuncAttributeMaxDynamicSharedMemorySize, smem);
    flash_attn<<<dim3(SEQ/64, BATCH*NHEAD), 256, smem>>>(q, k, v, ao);

    // 4) output projection (tensor cores, mma.sync)
    split_rows<<<(BT*512 + 255)/256, 256>>>(ao, Aao, BT);
    gemm_hmma<<<dim3(EMB/128, BT/128), 256, GEMM_SMEM>>>(Aao, Bout, bout, out, EMB);
}